// round 13
// baseline (speedup 1.0000x reference)
#include <cuda_runtime.h>
#include <stdint.h>

#define N0   292864
#define N1V  11264
#define NBV  1024
#define FIN  602
#define FH   256
#define FOUT 41
#define E1V  281600
#define E2V  10240
#define WIN  19    // 32-bit words holding 602 bits
#define WSTR 20    // padded stride (word 19 == 0)
#define WH   8     // words for 256 bits
#define NPL  7     // bit planes (counts <= 127)
#define KA   1216  // K dim: [0,608) = cnt part, [608,1216) = self-sign part
#define NTHR 512
#define TILES (N1V / 32)   // 352

// ---------------- device scratch (static, allocation-free) ----------------
static __device__ __align__(16) uint32_t g_xb [(size_t)N0  * WSTR];   // 23.4 MB
static __device__ __align__(16) int8_t   g_cA [(size_t)N1V * KA];     // 13.7 MB
static __device__ __align__(16) int8_t   g_sw [(size_t)FH  * KA];     // 311 KB
static __device__ __align__(16) uint32_t g_hb [N1V * WH];
static __device__ int g_deg1[N1V];          // zero at load; re-zeroed each call (ph6)
static __device__ int g_deg2[NBV];          // zero at load; re-zeroed each call (ph6)
static __device__ int g_off1[N1V + 1], g_cur1[N1V];
static __device__ int g_off2[NBV + 1], g_cur2[NBV];
static __device__ int g_csr1[E1V], g_csr2[E2V];
static __device__ unsigned char g_mask[N0]; // zero at load; only 1s set (idempotent)
static __device__ float g_al1[FH], g_ar1[FH];
static __device__ int   g_ws1[FH];
static __device__ __align__(16) uint32_t g_wl2[FOUT * WH], g_wr2[FOUT * WH];
static __device__ float g_al2[FOUT], g_ar2[FOUT];
static __device__ int   g_ws2[FOUT];

// software grid barrier (all blocks co-resident: grid == #SMs, 1 block/SM)
static __device__ int g_bar_count;
static __device__ volatile int g_bar_gen;

static __device__ __forceinline__ void gsync() {
    __syncthreads();
    if (threadIdx.x == 0) {
        int gen = g_bar_gen;
        __threadfence();
        if (atomicAdd(&g_bar_count, 1) == (int)gridDim.x - 1) {
            g_bar_count = 0;
            __threadfence();
            g_bar_gen = gen + 1;
        } else {
            while (g_bar_gen == gen) __nanosleep(64);
        }
        __threadfence();
    }
    __syncthreads();
}

static __device__ __forceinline__ int warp_is64(const void* p) {
    const unsigned* u = (const unsigned*)p;
    unsigned lane = threadIdx.x & 31;
    int z = 1;
    if (lane < 16) z = (u[2 * lane + 1] == 0u) ? 1 : 0;
    return __all_sync(0xffffffffu, z) ? 1 : 0;
}
static __device__ __forceinline__ int eget2(const void* p, long long i, int is64) {
    return is64 ? (int)((const long long*)p)[i] : ((const int*)p)[i];
}

#define RIPPLE(c) do { uint32_t t_;            \
    t_ = p0 & (c); p0 ^= (c); (c) = t_;        \
    t_ = p1 & (c); p1 ^= (c); (c) = t_;        \
    t_ = p2 & (c); p2 ^= (c); (c) = t_;        \
    t_ = p3 & (c); p3 ^= (c); (c) = t_;        \
    t_ = p4 & (c); p4 ^= (c); (c) = t_;        \
    t_ = p5 & (c); p5 ^= (c); (c) = t_;        \
    p6 ^= (c); } while (0)

// spread low 4 bits into bytes 0..3 (bit i -> byte i). 4-bit mask load-bearing.
static __device__ __forceinline__ uint32_t spread4(uint32_t n) {
    return ((n & 0xFu) * 0x00204081u) & 0x01010101u;
}

#define MMA_S8(c, A0, A1, A2, A3, B0, B1)                                   \
    asm volatile("mma.sync.aligned.m16n8k32.row.col.s32.s8.s8.s32 "         \
        "{%0,%1,%2,%3}, {%4,%5,%6,%7}, {%8,%9}, {%0,%1,%2,%3};"             \
        : "+r"(c[0]), "+r"(c[1]), "+r"(c[2]), "+r"(c[3])                    \
        : "r"(A0), "r"(A1), "r"(A2), "r"(A3), "r"(B0), "r"(B1))

// ============================ the one kernel ==============================
__global__ __launch_bounds__(NTHR, 1) void k_all(
    const float* __restrict__ x,
    const void* __restrict__ ei1, const void* __restrict__ ei2,
    const float* __restrict__ W1l, const float* __restrict__ W1r,
    const float* __restrict__ b1,
    const float* __restrict__ W2l, const float* __restrict__ W2r,
    const float* __restrict__ b2,
    float* __restrict__ out)
{
    __shared__ int   s_wsum[16];
    __shared__ float sh[32][257];   // gemm epilogue staging (33KB)

    const int tid = threadIdx.x, lane = tid & 31, wid = tid >> 5;
    const int GT = gridDim.x * NTHR;          // total threads
    const int TW = gridDim.x * (NTHR / 32);   // total warps
    const int gt = blockIdx.x * NTHR + tid;
    const int gw = blockIdx.x * (NTHR / 32) + wid;

    // ---------------- phase 1: weights + hist ----------------
    for (int g2w = gw; g2w < 2 * FH + 2 * FOUT; g2w += TW) {
        if (g2w < 2 * FH) {
            const float* W  = (g2w < FH) ? W1l : W1r;
            float*       AL = (g2w < FH) ? g_al1 : g_ar1;
            int j    = (g2w < FH) ? g2w : g2w - FH;
            int koff = (g2w < FH) ? 0 : 608;
            float asum = 0.f; int pos = 0;
            for (int k = 0; k < WIN; k++) {
                int f = k * 32 + lane;
                float w = (f < FIN) ? W[j * FIN + f] : 0.f;
                bool p = (f < FIN) && (w > 0.f);
                if (f < FIN) g_sw[(size_t)j * KA + koff + f] = p ? (int8_t)1 : (int8_t)-1;
                asum += fabsf(w);
                pos  += p ? 1 : 0;
            }
            if (lane < 6) g_sw[(size_t)j * KA + koff + FIN + lane] = 0;
            for (int o = 16; o; o >>= 1) asum += __shfl_xor_sync(0xffffffffu, asum, o);
            pos = __reduce_add_sync(0xffffffffu, pos);
            if (lane == 0) {
                AL[j] = asum / (float)FIN;
                if (g2w < FH) g_ws1[j] = 2 * pos - FIN;
            }
        } else {
            int q = g2w - 2 * FH;
            const float* W  = (q < FOUT) ? W2l : W2r;
            uint32_t*    WB = (q < FOUT) ? g_wl2 : g_wr2;
            float*       AL = (q < FOUT) ? g_al2 : g_ar2;
            int j = (q < FOUT) ? q : q - FOUT;
            float asum = 0.f; int pos = 0;
            for (int k = 0; k < WH; k++) {
                int f = k * 32 + lane;
                float w = W[j * FH + f];
                bool p = (w > 0.f);
                uint32_t bb = __ballot_sync(0xffffffffu, p);
                if (lane == 0) WB[j * WH + k] = bb;
                asum += fabsf(w);
                pos  += p ? 1 : 0;
            }
            for (int o = 16; o; o >>= 1) asum += __shfl_xor_sync(0xffffffffu, asum, o);
            pos = __reduce_add_sync(0xffffffffu, pos);
            if (lane == 0) {
                AL[j] = asum / (float)FH;
                if (q < FOUT) g_ws2[j] = 2 * pos - FH;
            }
        }
    }
    {
        int is64 = warp_is64(ei1);
        for (int e = gt; e < E1V; e += GT) {
            int d = eget2(ei1, (long long)E1V + e, is64);
            atomicAdd(&g_deg1[d], 1);
            int s = eget2(ei1, e, is64);
            g_mask[s] = 1;
        }
        for (int e = gt; e < E2V; e += GT) {
            int d = eget2(ei2, (long long)E2V + e, is64);
            atomicAdd(&g_deg2[d], 1);
        }
    }
    gsync();

    // ---------------- phase 2: prefix scans (blocks 0,1) ----------------
    if (blockIdx.x == 0) {          // N1V = 512 * 22
        int loc[22]; int s = 0;
#pragma unroll
        for (int k = 0; k < 22; k++) { loc[k] = s; s += g_deg1[tid * 22 + k]; }
        int v = s;
        for (int o = 1; o < 32; o <<= 1) {
            int u = __shfl_up_sync(0xffffffffu, v, o);
            if (lane >= o) v += u;
        }
        if (lane == 31) s_wsum[wid] = v;
        __syncthreads();
        if (wid == 0 && lane < 16) {
            int ws = s_wsum[lane];
            for (int o = 1; o < 16; o <<= 1) {
                int u = __shfl_up_sync(0x0000ffffu, ws, o);
                if (lane >= o) ws += u;
            }
            s_wsum[lane] = ws;
        }
        __syncthreads();
        int ex = ((wid > 0) ? s_wsum[wid - 1] : 0) + v - s;
#pragma unroll
        for (int k = 0; k < 22; k++) {
            g_off1[tid * 22 + k] = ex + loc[k];
            g_cur1[tid * 22 + k] = ex + loc[k];
        }
        if (tid == NTHR - 1) g_off1[N1V] = s_wsum[15];
    } else if (blockIdx.x == 1) {   // NBV = 512 * 2
        int loc[2]; int s = 0;
#pragma unroll
        for (int k = 0; k < 2; k++) { loc[k] = s; s += g_deg2[tid * 2 + k]; }
        int v = s;
        for (int o = 1; o < 32; o <<= 1) {
            int u = __shfl_up_sync(0xffffffffu, v, o);
            if (lane >= o) v += u;
        }
        if (lane == 31) s_wsum[wid] = v;
        __syncthreads();
        if (wid == 0 && lane < 16) {
            int ws = s_wsum[lane];
            for (int o = 1; o < 16; o <<= 1) {
                int u = __shfl_up_sync(0x0000ffffu, ws, o);
                if (lane >= o) ws += u;
            }
            s_wsum[lane] = ws;
        }
        __syncthreads();
        int ex = ((wid > 0) ? s_wsum[wid - 1] : 0) + v - s;
#pragma unroll
        for (int k = 0; k < 2; k++) {
            g_off2[tid * 2 + k] = ex + loc[k];
            g_cur2[tid * 2 + k] = ex + loc[k];
        }
        if (tid == NTHR - 1) g_off2[NBV] = s_wsum[15];
    }
    gsync();

    // ---------------- phase 3: scatter + bin ----------------
    {
        int is64 = warp_is64(ei1);
        for (int e = gt; e < E1V; e += GT) {
            int d = eget2(ei1, (long long)E1V + e, is64);
            int s = eget2(ei1, e, is64);
            int p = atomicAdd(&g_cur1[d], 1);
            g_csr1[p] = s;
        }
        for (int e = gt; e < E2V; e += GT) {
            int d = eget2(ei2, (long long)E2V + e, is64);
            int s = eget2(ei2, e, is64);
            int p = atomicAdd(&g_cur2[d], 1);
            g_csr2[p] = s;
        }
    }
    // bin: 2 rows per warp iteration (38 loads in flight)
    for (int pr = gw; pr < N0 / 2; pr += TW) {
        int r0 = pr * 2, r1 = r0 + 1;
        bool need0 = (r0 < N1V) || (g_mask[r0] != 0);
        bool need1 = (r1 < N1V) || (g_mask[r1] != 0);
        if (!(need0 || need1)) continue;
        const float* x0 = x + (size_t)r0 * FIN;
        const float* x1 = x + (size_t)r1 * FIN;
        float a[WIN], bvals[WIN]; float sa = 0.f, sb = 0.f;
#pragma unroll
        for (int k = 0; k < WIN; k++) {
            int f = k * 32 + lane;
            a[k]     = (need0 && f < FIN) ? __ldcs(x0 + f) : 0.f;
            bvals[k] = (need1 && f < FIN) ? __ldcs(x1 + f) : 0.f;
            sa += a[k]; sb += bvals[k];
        }
        for (int o = 16; o; o >>= 1) {
            sa += __shfl_xor_sync(0xffffffffu, sa, o);
            sb += __shfl_xor_sync(0xffffffffu, sb, o);
        }
        float ma = sa * (1.f / (float)FIN), mb = sb * (1.f / (float)FIN);
        if (need0) {
            uint32_t myw = 0;
#pragma unroll
            for (int k = 0; k < WIN; k++) {
                uint32_t bb = __ballot_sync(0xffffffffu, ((k * 32 + lane) < FIN) && (a[k] > ma));
                if (lane == k) myw = bb;
            }
            if (lane < WSTR) g_xb[(size_t)r0 * WSTR + lane] = (lane < WIN) ? myw : 0u;
        }
        if (need1) {
            uint32_t myw = 0;
#pragma unroll
            for (int k = 0; k < WIN; k++) {
                uint32_t bb = __ballot_sync(0xffffffffu, ((k * 32 + lane) < FIN) && (bvals[k] > mb));
                if (lane == k) myw = bb;
            }
            if (lane < WSTR) g_xb[(size_t)r1 * WSTR + lane] = (lane < WIN) ? myw : 0u;
        }
    }
    gsync();

    // ---------------- phase 4: agg1 (bit-sliced) + A expand ----------------
    for (int row = gw; row < N1V; row += TW) {
        int beg = g_off1[row], d = g_deg1[row];
        uint32_t p0 = 0, p1 = 0, p2 = 0, p3 = 0, p4 = 0, p5 = 0, p6 = 0;
        bool act = (lane < WIN);
        int e = 0;
        for (; e + 4 <= d; e += 4) {
            int s0 = __ldg(&g_csr1[beg + e + 0]);
            int s1 = __ldg(&g_csr1[beg + e + 1]);
            int s2 = __ldg(&g_csr1[beg + e + 2]);
            int s3 = __ldg(&g_csr1[beg + e + 3]);
            uint32_t c0 = act ? __ldg(&g_xb[(size_t)s0 * WSTR + lane]) : 0u;
            uint32_t c1 = act ? __ldg(&g_xb[(size_t)s1 * WSTR + lane]) : 0u;
            uint32_t c2 = act ? __ldg(&g_xb[(size_t)s2 * WSTR + lane]) : 0u;
            uint32_t c3 = act ? __ldg(&g_xb[(size_t)s3 * WSTR + lane]) : 0u;
            RIPPLE(c0); RIPPLE(c1); RIPPLE(c2); RIPPLE(c3);
        }
        for (; e < d; e++) {
            int s = __ldg(&g_csr1[beg + e]);
            uint32_t c = act ? __ldg(&g_xb[(size_t)s * WSTR + lane]) : 0u;
            RIPPLE(c);
        }
        if (act) {
            uint32_t xw = g_xb[(size_t)row * WSTR + lane];
            uint32_t* outw = (uint32_t*)(g_cA + (size_t)row * KA);
#pragma unroll
            for (int w = 0; w < 8; w++) {
                uint32_t cw =  spread4(p0 >> (4 * w))
                            | (spread4(p1 >> (4 * w)) << 1)
                            | (spread4(p2 >> (4 * w)) << 2)
                            | (spread4(p3 >> (4 * w)) << 3)
                            | (spread4(p4 >> (4 * w)) << 4)
                            | (spread4(p5 >> (4 * w)) << 5)
                            | (spread4(p6 >> (4 * w)) << 6);
                uint32_t sp = spread4(xw >> (4 * w));
                uint32_t sw = sp | ((sp ^ 0x01010101u) * 0xFFu);
                int f0 = lane * 32 + w * 4;
                int vnum = FIN - f0;
                uint32_t vm = (vnum >= 4) ? 0xFFFFFFFFu :
                              ((vnum <= 0) ? 0u : ((1u << (8 * vnum)) - 1u));
                outw[lane * 8 + w]       = cw;
                outw[152 + lane * 8 + w] = sw & vm;
            }
        }
    }
    gsync();

    // ---------------- phase 5: IMMA gemm, 32-row tiles ----------------
    {
        int warp_m = wid & 1, warp_n = wid >> 1;    // 2M x 8N
        int g = lane >> 2, t = lane & 3;
        int m0l = warp_m * 16;
        int n0 = warp_n * 32;
        for (int tile = blockIdx.x; tile < TILES; tile += gridDim.x) {
            int m0 = tile * 32;
            int acc1[4][4], acc2[4][4];
#pragma unroll
            for (int f = 0; f < 4; f++)
#pragma unroll
                for (int i = 0; i < 4; i++) { acc1[f][i] = 0; acc2[f][i] = 0; }

            const int8_t* Ar0 = g_cA + (size_t)(m0 + m0l + g) * KA;
            const int8_t* Ar1 = Ar0 + (size_t)8 * KA;

#define K_HALF(ACC, KBASE)                                                      \
            for (int ks = 0; ks < 19; ks++) {                                   \
                int k0 = (KBASE) + ks * 32 + 4 * t;                             \
                int a0 = *(const int*)(Ar0 + k0);                               \
                int a1 = *(const int*)(Ar1 + k0);                               \
                int a2 = *(const int*)(Ar0 + k0 + 16);                          \
                int a3 = *(const int*)(Ar1 + k0 + 16);                          \
                _Pragma("unroll")                                               \
                for (int f = 0; f < 4; f++) {                                   \
                    const int8_t* Bp = g_sw + (size_t)(n0 + f * 8 + g) * KA + k0;\
                    int b0 = *(const int*)Bp;                                   \
                    int b1 = *(const int*)(Bp + 16);                            \
                    MMA_S8(ACC[f], a0, a1, a2, a3, b0, b1);                     \
                }                                                               \
            }
            K_HALF(acc1, 0)
            K_HALF(acc2, 608)
#undef K_HALF

            int rg0 = m0 + m0l + g;
            int cnt0 = g_deg1[rg0], cnt1 = g_deg1[rg0 + 8];
            float rc0 = cnt0 ? (1.f / (float)cnt0) : 1.f;
            float rc1 = cnt1 ? (1.f / (float)cnt1) : 1.f;
#pragma unroll
            for (int f = 0; f < 4; f++) {
#pragma unroll
                for (int i = 0; i < 4; i++) {
                    int col = n0 + f * 8 + 2 * t + (i & 1);
                    int cnt = (i < 2) ? cnt0 : cnt1;
                    float rc = (i < 2) ? rc0 : rc1;
                    int r = m0l + ((i < 2) ? g : g + 8);
                    float v = g_al1[col] * (float)(2 * acc1[f][i] - cnt * g_ws1[col]) * rc
                            + g_ar1[col] * (float)acc2[f][i] + b1[col];
                    sh[r][col] = fmaxf(v, 0.f);
                }
            }
            __syncthreads();
#pragma unroll
            for (int rr = 0; rr < 2; rr++) {
                int r = wid * 2 + rr;
                float hv[8]; float s = 0.f;
#pragma unroll
                for (int q = 0; q < 8; q++) { hv[q] = sh[r][q * 32 + lane]; s += hv[q]; }
                for (int o = 16; o; o >>= 1) s += __shfl_xor_sync(0xffffffffu, s, o);
                float mean = s * (1.f / (float)FH);
#pragma unroll
                for (int q = 0; q < 8; q++) {
                    uint32_t bits = __ballot_sync(0xffffffffu, hv[q] > mean);
                    if (lane == q) g_hb[(m0 + r) * WH + q] = bits;
                }
            }
            __syncthreads();
        }
    }
    gsync();

    // ---------------- phase 6: l2 (warp per target) + deg re-zero ----------
    for (int k = gt; k < N1V; k += GT) g_deg1[k] = 0;
    for (int i = gw; i < NBV; i += TW) {
        int cnt = g_deg2[i];
        int beg = g_off2[i];
        bool act = (lane < WH);
        uint32_t xw = act ? g_hb[(size_t)i * WH + lane] : 0u;
        uint32_t p0 = 0, p1 = 0, p2 = 0, p3 = 0, p4 = 0, p5 = 0, p6 = 0;
        int e = 0;
        for (; e + 4 <= cnt; e += 4) {
            int s0 = __ldg(&g_csr2[beg + e + 0]);
            int s1 = __ldg(&g_csr2[beg + e + 1]);
            int s2 = __ldg(&g_csr2[beg + e + 2]);
            int s3 = __ldg(&g_csr2[beg + e + 3]);
            uint32_t c0 = act ? __ldg(&g_hb[(size_t)s0 * WH + lane]) : 0u;
            uint32_t c1 = act ? __ldg(&g_hb[(size_t)s1 * WH + lane]) : 0u;
            uint32_t c2 = act ? __ldg(&g_hb[(size_t)s2 * WH + lane]) : 0u;
            uint32_t c3 = act ? __ldg(&g_hb[(size_t)s3 * WH + lane]) : 0u;
            RIPPLE(c0); RIPPLE(c1); RIPPLE(c2); RIPPLE(c3);
        }
        for (; e < cnt; e++) {
            int s = __ldg(&g_csr2[beg + e]);
            uint32_t c = act ? __ldg(&g_hb[(size_t)s * WH + lane]) : 0u;
            RIPPLE(c);
        }
        int pa[7];
        pa[0] = __reduce_add_sync(0xffffffffu, __popc(p0));
        pa[1] = __reduce_add_sync(0xffffffffu, __popc(p1));
        pa[2] = __reduce_add_sync(0xffffffffu, __popc(p2));
        pa[3] = __reduce_add_sync(0xffffffffu, __popc(p3));
        pa[4] = __reduce_add_sync(0xffffffffu, __popc(p4));
        pa[5] = __reduce_add_sync(0xffffffffu, __popc(p5));
        pa[6] = __reduce_add_sync(0xffffffffu, __popc(p6));
        int np = cnt ? (32 - __clz(cnt)) : 0;

        int j = lane;                          // 0..31, all < FOUT
        bool has2 = lane < (FOUT - 32);        // 9 lanes
        int j2 = has2 ? (lane + 32) : 0;
        uint32_t wl[8], wr[8], wl2r[8], wr2r[8];
#pragma unroll
        for (int w = 0; w < 8; w++) {
            wl[w]   = g_wl2[j * WH + w];  wr[w]   = g_wr2[j * WH + w];
            wl2r[w] = g_wl2[j2 * WH + w]; wr2r[w] = g_wr2[j2 * WH + w];
        }
        int CW = 0, CW2 = 0;
#define PD(PP, P) if (np > P) { int s_ = 0, s2_ = 0;                          \
        _Pragma("unroll")                                                     \
        for (int w = 0; w < 8; w++) {                                         \
            uint32_t bw = __shfl_sync(0xffffffffu, PP, w);                    \
            s_  += __popc(bw & wl[w]);                                        \
            s2_ += __popc(bw & wl2r[w]);                                      \
        }                                                                     \
        CW  += (2 * s_  - pa[P]) << P;                                        \
        CW2 += (2 * s2_ - pa[P]) << P; }
        PD(p0, 0) PD(p1, 1) PD(p2, 2) PD(p3, 3) PD(p4, 4) PD(p5, 5) PD(p6, 6)
#undef PD
        int xr1 = 0, xr2 = 0;
#pragma unroll
        for (int w = 0; w < 8; w++) {
            uint32_t bx = __shfl_sync(0xffffffffu, xw, w);
            xr1 += __popc(bx ^ wr[w]);
            xr2 += __popc(bx ^ wr2r[w]);
        }
        int dot1 = FH - 2 * xr1, dotB = FH - 2 * xr2;
        float rc = cnt ? (1.f / (float)cnt) : 1.f;
        float v1 = (float)(2 * CW - cnt * g_ws2[j]) * rc * g_al2[j]
                 + (float)dot1 * g_ar2[j] + b2[j];
        float v2 = has2 ? ((float)(2 * CW2 - cnt * g_ws2[j2]) * rc * g_al2[j2]
                 + (float)dotB * g_ar2[j2] + b2[j2]) : -3.4e38f;
        float m = fmaxf(v1, v2);
        for (int o = 16; o; o >>= 1) m = fmaxf(m, __shfl_xor_sync(0xffffffffu, m, o));
        float se = expf(v1 - m) + (has2 ? expf(v2 - m) : 0.f);
        for (int o = 16; o; o >>= 1) se += __shfl_xor_sync(0xffffffffu, se, o);
        float lse = m + logf(se);
        out[i * FOUT + j] = v1 - lse;
        if (has2) out[i * FOUT + j2] = v2 - lse;
        if (lane == 0) g_deg2[i] = 0;
    }
}

// ---------------- host launcher: ONE kernel node ----------------
extern "C" void kernel_launch(void* const* d_in, const int* in_sizes, int n_in,
                              void* d_out, int out_size) {
    const float* x = nullptr;
    const void *ei1 = nullptr, *ei2 = nullptr;
    const float *W1l = nullptr, *W1r = nullptr, *b1 = nullptr;
    const float *W2l = nullptr, *W2r = nullptr, *b2 = nullptr;
    int c1 = 0, c2 = 0;
    for (int i = 0; i < n_in; i++) {
        switch (in_sizes[i]) {
            case 176304128: x   = (const float*)d_in[i]; break;
            case 563200:    ei1 = d_in[i]; break;
            case 20480:     ei2 = d_in[i]; break;
            case 154112:    if (c1++ == 0) W1l = (const float*)d_in[i];
                            else           W1r = (const float*)d_in[i]; break;
            case 256:       b1  = (const float*)d_in[i]; break;
            case 10496:     if (c2++ == 0) W2l = (const float*)d_in[i];
                            else           W2r = (const float*)d_in[i]; break;
            case 41:        b2  = (const float*)d_in[i]; break;
            default: break;
        }
    }

    static int nsm = 0;
    if (nsm == 0) {
        cudaDeviceGetAttribute(&nsm, cudaDevAttrMultiProcessorCount, 0);
        if (nsm <= 0) nsm = 148;
    }
    // grid == #SMs, 1 block/SM (<=128 regs, 33KB smem) -> all co-resident,
    // software grid barrier is safe.
    k_all<<<nsm, NTHR>>>(x, ei1, ei2, W1l, W1r, b1, W2l, W2r, b2, (float*)d_out);
}

// round 14
// speedup vs baseline: 1.1260x; 1.1260x over previous
#include <cuda_runtime.h>
#include <stdint.h>

#define N0   292864
#define N1V  11264
#define NBV  1024
#define FIN  602
#define FH   256
#define FOUT 41
#define E1V  281600
#define E2V  10240
#define WIN  19    // 32-bit words holding 602 bits
#define WSTR 20    // padded stride (word 19 == 0)
#define WH   8     // words for 256 bits
#define KA   1216  // K dim: [0,608) = cnt part, [608,1216) = self-sign part
#define NTHR 512
#define TILES (N1V / 32)   // 352

// ---------------- device scratch (static, allocation-free) ----------------
static __device__ __align__(16) uint32_t g_xb [(size_t)N0  * WSTR];   // 23.4 MB
static __device__ __align__(16) int8_t   g_cA [(size_t)N1V * KA];     // 13.7 MB
static __device__ __align__(16) int8_t   g_sw [(size_t)FH  * KA];     // 311 KB
static __device__ __align__(16) uint32_t g_hb [N1V * WH];
static __device__ int g_deg1[N1V];          // zero at load; re-zeroed each call
static __device__ int g_deg2[NBV];          // zero at load; re-zeroed each call
static __device__ int g_off1[N1V + 1], g_cur1[N1V];
static __device__ int g_off2[NBV + 1], g_cur2[NBV];
static __device__ int g_csr1[E1V], g_csr2[E2V];
static __device__ unsigned char g_mask[N0]; // zero at load; only 1s set (idempotent)
static __device__ float g_al1[FH], g_ar1[FH];
static __device__ int   g_ws1[FH];
static __device__ __align__(16) uint32_t g_wl2[FOUT * WH], g_wr2[FOUT * WH];
static __device__ float g_al2[FOUT], g_ar2[FOUT];
static __device__ int   g_ws2[FOUT];

// software grid barriers (separate state per persistent kernel; both kernels
// end with their counter back at 0 and an even total of gen increments is not
// required -- gen only ever increments, parity-free wait)
static __device__ int g_barA_count;  static __device__ volatile int g_barA_gen;
static __device__ int g_barB_count;  static __device__ volatile int g_barB_gen;

static __device__ __forceinline__ void gsyncx(int* cnt, volatile int* gen_p) {
    __syncthreads();
    if (threadIdx.x == 0) {
        int gen = *gen_p;
        __threadfence();
        if (atomicAdd(cnt, 1) == (int)gridDim.x - 1) {
            *cnt = 0;
            __threadfence();
            *gen_p = gen + 1;
        } else {
            while (*gen_p == gen) __nanosleep(64);
        }
        __threadfence();
    }
    __syncthreads();
}

static __device__ __forceinline__ int warp_is64(const void* p) {
    const unsigned* u = (const unsigned*)p;
    unsigned lane = threadIdx.x & 31;
    int z = 1;
    if (lane < 16) z = (u[2 * lane + 1] == 0u) ? 1 : 0;
    return __all_sync(0xffffffffu, z) ? 1 : 0;
}
static __device__ __forceinline__ int eget2(const void* p, long long i, int is64) {
    return is64 ? (int)((const long long*)p)[i] : ((const int*)p)[i];
}

#define RIPPLE(c) do { uint32_t t_;            \
    t_ = p0 & (c); p0 ^= (c); (c) = t_;        \
    t_ = p1 & (c); p1 ^= (c); (c) = t_;        \
    t_ = p2 & (c); p2 ^= (c); (c) = t_;        \
    t_ = p3 & (c); p3 ^= (c); (c) = t_;        \
    t_ = p4 & (c); p4 ^= (c); (c) = t_;        \
    t_ = p5 & (c); p5 ^= (c); (c) = t_;        \
    p6 ^= (c); } while (0)

// spread low 4 bits into bytes 0..3 (bit i -> byte i). 4-bit mask load-bearing.
static __device__ __forceinline__ uint32_t spread4(uint32_t n) {
    return ((n & 0xFu) * 0x00204081u) & 0x01010101u;
}

#define MMA_S8(c, A0, A1, A2, A3, B0, B1)                                   \
    asm volatile("mma.sync.aligned.m16n8k32.row.col.s32.s8.s8.s32 "         \
        "{%0,%1,%2,%3}, {%4,%5,%6,%7}, {%8,%9}, {%0,%1,%2,%3};"             \
        : "+r"(c[0]), "+r"(c[1]), "+r"(c[2]), "+r"(c[3])                    \
        : "r"(A0), "r"(A1), "r"(A2), "r"(A3), "r"(B0), "r"(B1))

// ================= k_pre: weights + hist -> scan -> scatter ================
__global__ __launch_bounds__(NTHR, 1) void k_pre(
    const void* __restrict__ ei1, const void* __restrict__ ei2,
    const float* __restrict__ W1l, const float* __restrict__ W1r,
    const float* __restrict__ W2l, const float* __restrict__ W2r)
{
    __shared__ int s_wsum[16];
    const int tid = threadIdx.x, lane = tid & 31, wid = tid >> 5;
    const int GT = gridDim.x * NTHR;
    const int TW = gridDim.x * (NTHR / 32);
    const int gt = blockIdx.x * NTHR + tid;
    const int gw = blockIdx.x * (NTHR / 32) + wid;

    // ---- phase 1: weights + hist ----
    for (int g2w = gw; g2w < 2 * FH + 2 * FOUT; g2w += TW) {
        if (g2w < 2 * FH) {
            const float* W  = (g2w < FH) ? W1l : W1r;
            float*       AL = (g2w < FH) ? g_al1 : g_ar1;
            int j    = (g2w < FH) ? g2w : g2w - FH;
            int koff = (g2w < FH) ? 0 : 608;
            float asum = 0.f; int pos = 0;
            for (int k = 0; k < WIN; k++) {
                int f = k * 32 + lane;
                float w = (f < FIN) ? W[j * FIN + f] : 0.f;
                bool p = (f < FIN) && (w > 0.f);
                if (f < FIN) g_sw[(size_t)j * KA + koff + f] = p ? (int8_t)1 : (int8_t)-1;
                asum += fabsf(w);
                pos  += p ? 1 : 0;
            }
            if (lane < 6) g_sw[(size_t)j * KA + koff + FIN + lane] = 0;
            for (int o = 16; o; o >>= 1) asum += __shfl_xor_sync(0xffffffffu, asum, o);
            pos = __reduce_add_sync(0xffffffffu, pos);
            if (lane == 0) {
                AL[j] = asum / (float)FIN;
                if (g2w < FH) g_ws1[j] = 2 * pos - FIN;
            }
        } else {
            int q = g2w - 2 * FH;
            const float* W  = (q < FOUT) ? W2l : W2r;
            uint32_t*    WB = (q < FOUT) ? g_wl2 : g_wr2;
            float*       AL = (q < FOUT) ? g_al2 : g_ar2;
            int j = (q < FOUT) ? q : q - FOUT;
            float asum = 0.f; int pos = 0;
            for (int k = 0; k < WH; k++) {
                int f = k * 32 + lane;
                float w = W[j * FH + f];
                bool p = (w > 0.f);
                uint32_t bb = __ballot_sync(0xffffffffu, p);
                if (lane == 0) WB[j * WH + k] = bb;
                asum += fabsf(w);
                pos  += p ? 1 : 0;
            }
            for (int o = 16; o; o >>= 1) asum += __shfl_xor_sync(0xffffffffu, asum, o);
            pos = __reduce_add_sync(0xffffffffu, pos);
            if (lane == 0) {
                AL[j] = asum / (float)FH;
                if (q < FOUT) g_ws2[j] = 2 * pos - FH;
            }
        }
    }
    {
        int is64 = warp_is64(ei1);
        for (int e = gt; e < E1V; e += GT) {
            int d = eget2(ei1, (long long)E1V + e, is64);
            atomicAdd(&g_deg1[d], 1);
            int s = eget2(ei1, e, is64);
            g_mask[s] = 1;
        }
        for (int e = gt; e < E2V; e += GT) {
            int d = eget2(ei2, (long long)E2V + e, is64);
            atomicAdd(&g_deg2[d], 1);
        }
    }
    gsyncx(&g_barA_count, &g_barA_gen);

    // ---- phase 2: scans (blocks 0,1) ----
    if (blockIdx.x == 0) {          // N1V = 512 * 22
        int loc[22]; int s = 0;
#pragma unroll
        for (int k = 0; k < 22; k++) { loc[k] = s; s += g_deg1[tid * 22 + k]; }
        int v = s;
        for (int o = 1; o < 32; o <<= 1) {
            int u = __shfl_up_sync(0xffffffffu, v, o);
            if (lane >= o) v += u;
        }
        if (lane == 31) s_wsum[wid] = v;
        __syncthreads();
        if (wid == 0 && lane < 16) {
            int ws = s_wsum[lane];
            for (int o = 1; o < 16; o <<= 1) {
                int u = __shfl_up_sync(0x0000ffffu, ws, o);
                if (lane >= o) ws += u;
            }
            s_wsum[lane] = ws;
        }
        __syncthreads();
        int ex = ((wid > 0) ? s_wsum[wid - 1] : 0) + v - s;
#pragma unroll
        for (int k = 0; k < 22; k++) {
            g_off1[tid * 22 + k] = ex + loc[k];
            g_cur1[tid * 22 + k] = ex + loc[k];
        }
        if (tid == NTHR - 1) g_off1[N1V] = s_wsum[15];
    } else if (blockIdx.x == 1) {   // NBV = 512 * 2
        int loc[2]; int s = 0;
#pragma unroll
        for (int k = 0; k < 2; k++) { loc[k] = s; s += g_deg2[tid * 2 + k]; }
        int v = s;
        for (int o = 1; o < 32; o <<= 1) {
            int u = __shfl_up_sync(0xffffffffu, v, o);
            if (lane >= o) v += u;
        }
        if (lane == 31) s_wsum[wid] = v;
        __syncthreads();
        if (wid == 0 && lane < 16) {
            int ws = s_wsum[lane];
            for (int o = 1; o < 16; o <<= 1) {
                int u = __shfl_up_sync(0x0000ffffu, ws, o);
                if (lane >= o) ws += u;
            }
            s_wsum[lane] = ws;
        }
        __syncthreads();
        int ex = ((wid > 0) ? s_wsum[wid - 1] : 0) + v - s;
#pragma unroll
        for (int k = 0; k < 2; k++) {
            g_off2[tid * 2 + k] = ex + loc[k];
            g_cur2[tid * 2 + k] = ex + loc[k];
        }
        if (tid == NTHR - 1) g_off2[NBV] = s_wsum[15];
    }
    gsyncx(&g_barA_count, &g_barA_gen);

    // ---- phase 3: scatter ----
    {
        int is64 = warp_is64(ei1);
        for (int e = gt; e < E1V; e += GT) {
            int d = eget2(ei1, (long long)E1V + e, is64);
            int s = eget2(ei1, e, is64);
            int p = atomicAdd(&g_cur1[d], 1);
            g_csr1[p] = s;
        }
        for (int e = gt; e < E2V; e += GT) {
            int d = eget2(ei2, (long long)E2V + e, is64);
            int s = eget2(ei2, e, is64);
            int p = atomicAdd(&g_cur2[d], 1);
            g_csr2[p] = s;
        }
    }
}

// ============ k_bin: wide, HBM-capped (proven 73us @ occ 74%) =============
__global__ __launch_bounds__(256) void k_bin(const float* __restrict__ x) {
    int wid = threadIdx.x >> 5, lane = threadIdx.x & 31;
    int row = blockIdx.x * 8 + wid;
    bool need = (row < N1V) || (g_mask[row] != 0);
    if (!need) return;
    const float* xr = x + (size_t)row * FIN;
    float v[WIN]; float s = 0.f;
#pragma unroll
    for (int k = 0; k < WIN; k++) {
        int f = k * 32 + lane;
        float val = (f < FIN) ? __ldcs(xr + f) : 0.f;
        v[k] = val; s += val;
    }
    for (int o = 16; o; o >>= 1) s += __shfl_xor_sync(0xffffffffu, s, o);
    float mean = s * (1.f / (float)FIN);
    uint32_t myw = 0;
#pragma unroll
    for (int k = 0; k < WIN; k++) {
        uint32_t b = __ballot_sync(0xffffffffu, ((k * 32 + lane) < FIN) && (v[k] > mean));
        if (lane == k) myw = b;
    }
    if (lane < WSTR) g_xb[(size_t)row * WSTR + lane] = (lane < WIN) ? myw : 0u;
}

// ================ k_post: agg1 -> IMMA gemm -> l2 + re-zero ================
__global__ __launch_bounds__(NTHR, 1) void k_post(
    const float* __restrict__ b1, const float* __restrict__ b2,
    float* __restrict__ out)
{
    __shared__ float sh[32][257];
    const int tid = threadIdx.x, lane = tid & 31, wid = tid >> 5;
    const int GT = gridDim.x * NTHR;
    const int TW = gridDim.x * (NTHR / 32);
    const int gt = blockIdx.x * NTHR + tid;
    const int gw = blockIdx.x * (NTHR / 32) + wid;

    // ---- phase A: agg1 (bit-sliced) + int8 A expand ----
    for (int row = gw; row < N1V; row += TW) {
        int beg = g_off1[row], d = g_deg1[row];
        uint32_t p0 = 0, p1 = 0, p2 = 0, p3 = 0, p4 = 0, p5 = 0, p6 = 0;
        bool act = (lane < WIN);
        int e = 0;
        for (; e + 4 <= d; e += 4) {
            int s0 = __ldg(&g_csr1[beg + e + 0]);
            int s1 = __ldg(&g_csr1[beg + e + 1]);
            int s2 = __ldg(&g_csr1[beg + e + 2]);
            int s3 = __ldg(&g_csr1[beg + e + 3]);
            uint32_t c0 = act ? __ldg(&g_xb[(size_t)s0 * WSTR + lane]) : 0u;
            uint32_t c1 = act ? __ldg(&g_xb[(size_t)s1 * WSTR + lane]) : 0u;
            uint32_t c2 = act ? __ldg(&g_xb[(size_t)s2 * WSTR + lane]) : 0u;
            uint32_t c3 = act ? __ldg(&g_xb[(size_t)s3 * WSTR + lane]) : 0u;
            RIPPLE(c0); RIPPLE(c1); RIPPLE(c2); RIPPLE(c3);
        }
        for (; e < d; e++) {
            int s = __ldg(&g_csr1[beg + e]);
            uint32_t c = act ? __ldg(&g_xb[(size_t)s * WSTR + lane]) : 0u;
            RIPPLE(c);
        }
        if (act) {
            uint32_t xw = g_xb[(size_t)row * WSTR + lane];
            uint32_t* outw = (uint32_t*)(g_cA + (size_t)row * KA);
#pragma unroll
            for (int w = 0; w < 8; w++) {
                uint32_t cw =  spread4(p0 >> (4 * w))
                            | (spread4(p1 >> (4 * w)) << 1)
                            | (spread4(p2 >> (4 * w)) << 2)
                            | (spread4(p3 >> (4 * w)) << 3)
                            | (spread4(p4 >> (4 * w)) << 4)
                            | (spread4(p5 >> (4 * w)) << 5)
                            | (spread4(p6 >> (4 * w)) << 6);
                uint32_t sp = spread4(xw >> (4 * w));
                uint32_t sw = sp | ((sp ^ 0x01010101u) * 0xFFu);
                int f0 = lane * 32 + w * 4;
                int vnum = FIN - f0;
                uint32_t vm = (vnum >= 4) ? 0xFFFFFFFFu :
                              ((vnum <= 0) ? 0u : ((1u << (8 * vnum)) - 1u));
                outw[lane * 8 + w]       = cw;
                outw[152 + lane * 8 + w] = sw & vm;
            }
        }
    }
    gsyncx(&g_barB_count, &g_barB_gen);

    // ---- phase B: IMMA gemm, 32-row tiles ----
    {
        int warp_m = wid & 1, warp_n = wid >> 1;    // 2M x 8N
        int g = lane >> 2, t = lane & 3;
        int m0l = warp_m * 16;
        int n0 = warp_n * 32;
        for (int tile = blockIdx.x; tile < TILES; tile += gridDim.x) {
            int m0 = tile * 32;
            int acc1[4][4], acc2[4][4];
#pragma unroll
            for (int f = 0; f < 4; f++)
#pragma unroll
                for (int i = 0; i < 4; i++) { acc1[f][i] = 0; acc2[f][i] = 0; }

            const int8_t* Ar0 = g_cA + (size_t)(m0 + m0l + g) * KA;
            const int8_t* Ar1 = Ar0 + (size_t)8 * KA;

#define K_HALF(ACC, KBASE)                                                      \
            for (int ks = 0; ks < 19; ks++) {                                   \
                int k0 = (KBASE) + ks * 32 + 4 * t;                             \
                int a0 = *(const int*)(Ar0 + k0);                               \
                int a1 = *(const int*)(Ar1 + k0);                               \
                int a2 = *(const int*)(Ar0 + k0 + 16);                          \
                int a3 = *(const int*)(Ar1 + k0 + 16);                          \
                _Pragma("unroll")                                               \
                for (int f = 0; f < 4; f++) {                                   \
                    const int8_t* Bp = g_sw + (size_t)(n0 + f * 8 + g) * KA + k0;\
                    int b0 = *(const int*)Bp;                                   \
                    int b1 = *(const int*)(Bp + 16);                            \
                    MMA_S8(ACC[f], a0, a1, a2, a3, b0, b1);                     \
                }                                                               \
            }
            K_HALF(acc1, 0)
            K_HALF(acc2, 608)
#undef K_HALF

            int rg0 = m0 + m0l + g;
            int cnt0 = g_deg1[rg0], cnt1 = g_deg1[rg0 + 8];
            float rc0 = cnt0 ? (1.f / (float)cnt0) : 1.f;
            float rc1 = cnt1 ? (1.f / (float)cnt1) : 1.f;
#pragma unroll
            for (int f = 0; f < 4; f++) {
#pragma unroll
                for (int i = 0; i < 4; i++) {
                    int col = n0 + f * 8 + 2 * t + (i & 1);
                    int cnt = (i < 2) ? cnt0 : cnt1;
                    float rc = (i < 2) ? rc0 : rc1;
                    int r = m0l + ((i < 2) ? g : g + 8);
                    float v = g_al1[col] * (float)(2 * acc1[f][i] - cnt * g_ws1[col]) * rc
                            + g_ar1[col] * (float)acc2[f][i] + b1[col];
                    sh[r][col] = fmaxf(v, 0.f);
                }
            }
            __syncthreads();
#pragma unroll
            for (int rr = 0; rr < 2; rr++) {
                int r = wid * 2 + rr;
                float hv[8]; float s = 0.f;
#pragma unroll
                for (int q = 0; q < 8; q++) { hv[q] = sh[r][q * 32 + lane]; s += hv[q]; }
                for (int o = 16; o; o >>= 1) s += __shfl_xor_sync(0xffffffffu, s, o);
                float mean = s * (1.f / (float)FH);
#pragma unroll
                for (int q = 0; q < 8; q++) {
                    uint32_t bits = __ballot_sync(0xffffffffu, hv[q] > mean);
                    if (lane == q) g_hb[(m0 + r) * WH + q] = bits;
                }
            }
            __syncthreads();
        }
    }
    gsyncx(&g_barB_count, &g_barB_gen);

    // ---- phase C: l2 (warp per target) + deg re-zero ----
    for (int k = gt; k < N1V; k += GT) g_deg1[k] = 0;
    for (int i = gw; i < NBV; i += TW) {
        int cnt = g_deg2[i];
        int beg = g_off2[i];
        bool act = (lane < WH);
        uint32_t xw = act ? g_hb[(size_t)i * WH + lane] : 0u;
        uint32_t p0 = 0, p1 = 0, p2 = 0, p3 = 0, p4 = 0, p5 = 0, p6 = 0;
        int e = 0;
        for (; e + 4 <= cnt; e += 4) {
            int s0 = __ldg(&g_csr2[beg + e + 0]);
            int s1 = __ldg(&g_csr2[beg + e + 1]);
            int s2 = __ldg(&g_csr2[beg + e + 2]);
            int s3 = __ldg(&g_csr2[beg + e + 3]);
            uint32_t c0 = act ? __ldg(&g_hb[(size_t)s0 * WH + lane]) : 0u;
            uint32_t c1 = act ? __ldg(&g_hb[(size_t)s1 * WH + lane]) : 0u;
            uint32_t c2 = act ? __ldg(&g_hb[(size_t)s2 * WH + lane]) : 0u;
            uint32_t c3 = act ? __ldg(&g_hb[(size_t)s3 * WH + lane]) : 0u;
            RIPPLE(c0); RIPPLE(c1); RIPPLE(c2); RIPPLE(c3);
        }
        for (; e < cnt; e++) {
            int s = __ldg(&g_csr2[beg + e]);
            uint32_t c = act ? __ldg(&g_hb[(size_t)s * WH + lane]) : 0u;
            RIPPLE(c);
        }
        int pa[7];
        pa[0] = __reduce_add_sync(0xffffffffu, __popc(p0));
        pa[1] = __reduce_add_sync(0xffffffffu, __popc(p1));
        pa[2] = __reduce_add_sync(0xffffffffu, __popc(p2));
        pa[3] = __reduce_add_sync(0xffffffffu, __popc(p3));
        pa[4] = __reduce_add_sync(0xffffffffu, __popc(p4));
        pa[5] = __reduce_add_sync(0xffffffffu, __popc(p5));
        pa[6] = __reduce_add_sync(0xffffffffu, __popc(p6));
        int np = cnt ? (32 - __clz(cnt)) : 0;

        int j = lane;
        bool has2 = lane < (FOUT - 32);
        int j2 = has2 ? (lane + 32) : 0;
        uint32_t wl[8], wr[8], wl2r[8], wr2r[8];
#pragma unroll
        for (int w = 0; w < 8; w++) {
            wl[w]   = g_wl2[j * WH + w];  wr[w]   = g_wr2[j * WH + w];
            wl2r[w] = g_wl2[j2 * WH + w]; wr2r[w] = g_wr2[j2 * WH + w];
        }
        int CW = 0, CW2 = 0;
#define PD(PP, P) if (np > P) { int s_ = 0, s2_ = 0;                          \
        _Pragma("unroll")                                                     \
        for (int w = 0; w < 8; w++) {                                         \
            uint32_t bw = __shfl_sync(0xffffffffu, PP, w);                    \
            s_  += __popc(bw & wl[w]);                                        \
            s2_ += __popc(bw & wl2r[w]);                                      \
        }                                                                     \
        CW  += (2 * s_  - pa[P]) << P;                                        \
        CW2 += (2 * s2_ - pa[P]) << P; }
        PD(p0, 0) PD(p1, 1) PD(p2, 2) PD(p3, 3) PD(p4, 4) PD(p5, 5) PD(p6, 6)
#undef PD
        int xr1 = 0, xr2 = 0;
#pragma unroll
        for (int w = 0; w < 8; w++) {
            uint32_t bx = __shfl_sync(0xffffffffu, xw, w);
            xr1 += __popc(bx ^ wr[w]);
            xr2 += __popc(bx ^ wr2r[w]);
        }
        int dot1 = FH - 2 * xr1, dotB = FH - 2 * xr2;
        float rc = cnt ? (1.f / (float)cnt) : 1.f;
        float v1 = (float)(2 * CW - cnt * g_ws2[j]) * rc * g_al2[j]
                 + (float)dot1 * g_ar2[j] + b2[j];
        float v2 = has2 ? ((float)(2 * CW2 - cnt * g_ws2[j2]) * rc * g_al2[j2]
                 + (float)dotB * g_ar2[j2] + b2[j2]) : -3.4e38f;
        float m = fmaxf(v1, v2);
        for (int o = 16; o; o >>= 1) m = fmaxf(m, __shfl_xor_sync(0xffffffffu, m, o));
        float se = expf(v1 - m) + (has2 ? expf(v2 - m) : 0.f);
        for (int o = 16; o; o >>= 1) se += __shfl_xor_sync(0xffffffffu, se, o);
        float lse = m + logf(se);
        out[i * FOUT + j] = v1 - lse;
        if (has2) out[i * FOUT + j2] = v2 - lse;
        if (lane == 0) g_deg2[i] = 0;
    }
}

// ---------------- host launcher: 3 kernel nodes ----------------
extern "C" void kernel_launch(void* const* d_in, const int* in_sizes, int n_in,
                              void* d_out, int out_size) {
    const float* x = nullptr;
    const void *ei1 = nullptr, *ei2 = nullptr;
    const float *W1l = nullptr, *W1r = nullptr, *b1 = nullptr;
    const float *W2l = nullptr, *W2r = nullptr, *b2 = nullptr;
    int c1 = 0, c2 = 0;
    for (int i = 0; i < n_in; i++) {
        switch (in_sizes[i]) {
            case 176304128: x   = (const float*)d_in[i]; break;
            case 563200:    ei1 = d_in[i]; break;
            case 20480:     ei2 = d_in[i]; break;
            case 154112:    if (c1++ == 0) W1l = (const float*)d_in[i];
                            else           W1r = (const float*)d_in[i]; break;
            case 256:       b1  = (const float*)d_in[i]; break;
            case 10496:     if (c2++ == 0) W2l = (const float*)d_in[i];
                            else           W2r = (const float*)d_in[i]; break;
            case 41:        b2  = (const float*)d_in[i]; break;
            default: break;
        }
    }

    static int nsm = 0;
    if (nsm == 0) {
        cudaDeviceGetAttribute(&nsm, cudaDevAttrMultiProcessorCount, 0);
        if (nsm <= 0) nsm = 148;
    }
    k_pre <<<nsm, NTHR>>>(ei1, ei2, W1l, W1r, W2l, W2r);
    k_bin <<<N0 / 8, 256>>>(x);
    k_post<<<nsm, NTHR>>>(b1, b2, (float*)d_out);
}

// round 15
// speedup vs baseline: 1.1917x; 1.0583x over previous
#include <cuda_runtime.h>
#include <stdint.h>

#define N0   292864
#define N1V  11264
#define NBV  1024
#define FIN  602
#define FH   256
#define FOUT 41
#define E1V  281600
#define E2V  10240
#define WIN  19    // 32-bit words holding 602 bits
#define WSTR 20    // padded stride (word 19 == 0)
#define WH   8     // words for 256 bits
#define NPL  7     // bit planes (counts <= 127)
#define KA   1216  // K dim: [0,608) = cnt part, [608,1216) = self-sign part

// ---------------- device scratch (static, allocation-free) ----------------
static __device__ __align__(16) uint32_t g_xb [(size_t)N0  * WSTR];   // 23.4 MB
static __device__ __align__(16) int8_t   g_cA [(size_t)N1V * KA];     // 13.7 MB
static __device__ __align__(16) int8_t   g_sw [(size_t)FH  * KA];     // 311 KB
static __device__ __align__(16) uint32_t g_hb [N1V * WH];
static __device__ int g_deg1[N1V];          // zero at load; re-zeroed by k_l2 tail
static __device__ int g_deg2[NBV];          // zero at load; re-zeroed by k_l2 tail
static __device__ int g_off1[N1V + 1], g_cur1[N1V];
static __device__ int g_off2[NBV + 1], g_cur2[NBV];
static __device__ int g_csr1[E1V], g_csr2[E2V];
static __device__ unsigned char g_mask[N0]; // zero at load; hist only sets 1s
static __device__ float g_al1[FH], g_ar1[FH];
static __device__ int   g_ws1[FH];
static __device__ __align__(16) uint32_t g_wl2[FOUT * WH], g_wr2[FOUT * WH];
static __device__ float g_al2[FOUT], g_ar2[FOUT];
static __device__ int   g_ws2[FOUT];

// warp-collective int64-vs-int32 detection (int64 < 2^31 -> zero high words)
static __device__ __forceinline__ int warp_is64(const void* p) {
    const unsigned* u = (const unsigned*)p;
    unsigned lane = threadIdx.x & 31;
    int z = 1;
    if (lane < 16) z = (u[2 * lane + 1] == 0u) ? 1 : 0;
    return __all_sync(0xffffffffu, z) ? 1 : 0;
}
static __device__ __forceinline__ int eget2(const void* p, long long i, int is64) {
    return is64 ? (int)((const long long*)p)[i] : ((const int*)p)[i];
}

#define RIPPLE(c) do { uint32_t t_;            \
    t_ = p0 & (c); p0 ^= (c); (c) = t_;        \
    t_ = p1 & (c); p1 ^= (c); (c) = t_;        \
    t_ = p2 & (c); p2 ^= (c); (c) = t_;        \
    t_ = p3 & (c); p3 ^= (c); (c) = t_;        \
    t_ = p4 & (c); p4 ^= (c); (c) = t_;        \
    t_ = p5 & (c); p5 ^= (c); (c) = t_;        \
    p6 ^= (c); } while (0)

// spread low 4 bits into bytes 0..3 (bit i -> byte i). 4-bit mask load-bearing.
static __device__ __forceinline__ uint32_t spread4(uint32_t n) {
    return ((n & 0xFu) * 0x00204081u) & 0x01010101u;
}

#define MMA_S8(c, A0, A1, A2, A3, B0, B1)                                   \
    asm volatile("mma.sync.aligned.m16n8k32.row.col.s32.s8.s8.s32 "         \
        "{%0,%1,%2,%3}, {%4,%5,%6,%7}, {%8,%9}, {%0,%1,%2,%3};"             \
        : "+r"(c[0]), "+r"(c[1]), "+r"(c[2]), "+r"(c[3])                    \
        : "r"(A0), "r"(A1), "r"(A2), "r"(A3), "r"(B0), "r"(B1))

// ---------------- kernels (all wide / high-occupancy) ----------------

__global__ void k_hist(const void* ei1, const void* ei2) {
    int is64 = warp_is64(ei1);
    int e = blockIdx.x * blockDim.x + threadIdx.x;
    if (e < E1V) {
        int d = eget2(ei1, (long long)E1V + e, is64);
        atomicAdd(&g_deg1[d], 1);
        int s = eget2(ei1, e, is64);
        g_mask[s] = 1;
    }
    if (e < E2V) {
        int d = eget2(ei2, (long long)E2V + e, is64);
        atomicAdd(&g_deg2[d], 1);
    }
}

__global__ void k_weights(const float* __restrict__ W1l, const float* __restrict__ W1r,
                          const float* __restrict__ W2l, const float* __restrict__ W2r) {
    int gw   = (blockIdx.x * blockDim.x + threadIdx.x) >> 5;
    int lane = threadIdx.x & 31;
    if (gw < 2 * FH) {
        const float* W  = (gw < FH) ? W1l : W1r;
        float*       AL = (gw < FH) ? g_al1 : g_ar1;
        int j    = (gw < FH) ? gw : gw - FH;
        int koff = (gw < FH) ? 0 : 608;
        float asum = 0.f; int pos = 0;
        for (int k = 0; k < WIN; k++) {
            int f = k * 32 + lane;
            float w = (f < FIN) ? W[j * FIN + f] : 0.f;
            bool p = (f < FIN) && (w > 0.f);
            if (f < FIN) g_sw[(size_t)j * KA + koff + f] = p ? (int8_t)1 : (int8_t)-1;
            asum += fabsf(w);
            pos  += p ? 1 : 0;
        }
        if (lane < 6) g_sw[(size_t)j * KA + koff + FIN + lane] = 0;  // pad
        for (int o = 16; o; o >>= 1) asum += __shfl_xor_sync(0xffffffffu, asum, o);
        pos = __reduce_add_sync(0xffffffffu, pos);
        if (lane == 0) {
            AL[j] = asum / (float)FIN;
            if (gw < FH) g_ws1[j] = 2 * pos - FIN;
        }
    } else if (gw < 2 * FH + 2 * FOUT) {
        int g2 = gw - 2 * FH;
        const float* W  = (g2 < FOUT) ? W2l : W2r;
        uint32_t*    WB = (g2 < FOUT) ? g_wl2 : g_wr2;
        float*       AL = (g2 < FOUT) ? g_al2 : g_ar2;
        int j = (g2 < FOUT) ? g2 : g2 - FOUT;
        float asum = 0.f; int pos = 0;
        for (int k = 0; k < WH; k++) {
            int f = k * 32 + lane;
            float w = W[j * FH + f];
            bool p = (w > 0.f);
            uint32_t b = __ballot_sync(0xffffffffu, p);
            if (lane == 0) WB[j * WH + k] = b;
            asum += fabsf(w);
            pos  += p ? 1 : 0;
        }
        for (int o = 16; o; o >>= 1) asum += __shfl_xor_sync(0xffffffffu, asum, o);
        pos = __reduce_add_sync(0xffffffffu, pos);
        if (lane == 0) {
            AL[j] = asum / (float)FH;
            if (g2 < FOUT) g_ws2[j] = 2 * pos - FH;
        }
    }
}

// per-row mean + sign + bitpack; skip rows never used downstream
__global__ __launch_bounds__(256) void k_bin(const float* __restrict__ x) {
    int wid = threadIdx.x >> 5, lane = threadIdx.x & 31;
    int row = blockIdx.x * 8 + wid;
    bool need = (row < N1V) || (g_mask[row] != 0);
    if (!need) return;
    const float* xr = x + (size_t)row * FIN;
    float v[WIN]; float s = 0.f;
#pragma unroll
    for (int k = 0; k < WIN; k++) {
        int f = k * 32 + lane;
        float val = (f < FIN) ? __ldcs(xr + f) : 0.f;
        v[k] = val; s += val;
    }
    for (int o = 16; o; o >>= 1) s += __shfl_xor_sync(0xffffffffu, s, o);
    float mean = s * (1.f / (float)FIN);
    uint32_t myw = 0;
#pragma unroll
    for (int k = 0; k < WIN; k++) {
        uint32_t b = __ballot_sync(0xffffffffu, ((k * 32 + lane) < FIN) && (v[k] > mean));
        if (lane == k) myw = b;
    }
    if (lane < WSTR) g_xb[(size_t)row * WSTR + lane] = (lane < WIN) ? myw : 0u;
}

// shuffle-based scans (3 syncs)
__global__ void k_scan() {
    __shared__ int wsum[32];
    int t = threadIdx.x, lane = t & 31, w = t >> 5;
    if (blockIdx.x == 0) {                 // N1V = 1024 * 11
        int loc[11]; int s = 0;
#pragma unroll
        for (int k = 0; k < 11; k++) { loc[k] = s; s += g_deg1[t * 11 + k]; }
        int v = s;
        for (int o = 1; o < 32; o <<= 1) {
            int u = __shfl_up_sync(0xffffffffu, v, o);
            if (lane >= o) v += u;
        }
        if (lane == 31) wsum[w] = v;
        __syncthreads();
        if (w == 0) {
            int ws = wsum[lane];
            for (int o = 1; o < 32; o <<= 1) {
                int u = __shfl_up_sync(0xffffffffu, ws, o);
                if (lane >= o) ws += u;
            }
            wsum[lane] = ws;
        }
        __syncthreads();
        int ex = ((w > 0) ? wsum[w - 1] : 0) + v - s;
#pragma unroll
        for (int k = 0; k < 11; k++) {
            g_off1[t * 11 + k] = ex + loc[k];
            g_cur1[t * 11 + k] = ex + loc[k];
        }
        if (t == 1023) g_off1[N1V] = wsum[31];
    } else {                               // NBV = 1024
        int s = g_deg2[t];
        int v = s;
        for (int o = 1; o < 32; o <<= 1) {
            int u = __shfl_up_sync(0xffffffffu, v, o);
            if (lane >= o) v += u;
        }
        if (lane == 31) wsum[w] = v;
        __syncthreads();
        if (w == 0) {
            int ws = wsum[lane];
            for (int o = 1; o < 32; o <<= 1) {
                int u = __shfl_up_sync(0xffffffffu, ws, o);
                if (lane >= o) ws += u;
            }
            wsum[lane] = ws;
        }
        __syncthreads();
        int ex = ((w > 0) ? wsum[w - 1] : 0) + v - s;
        g_off2[t] = ex; g_cur2[t] = ex;
        if (t == 1023) g_off2[NBV] = wsum[31];
    }
}

__global__ void k_scatter(const void* ei1, const void* ei2) {
    int is64 = warp_is64(ei1);
    int e = blockIdx.x * blockDim.x + threadIdx.x;
    if (e < E1V) {
        int d = eget2(ei1, (long long)E1V + e, is64);
        int s = eget2(ei1, e, is64);
        int p = atomicAdd(&g_cur1[d], 1);
        g_csr1[p] = s;
    }
    if (e < E2V) {
        int d = eget2(ei2, (long long)E2V + e, is64);
        int s = eget2(ei2, e, is64);
        int p = atomicAdd(&g_cur2[d], 1);
        g_csr2[p] = s;
    }
}

// layer-1 edge aggregation: bit-sliced ripple accumulation + int8 A expand
__global__ __launch_bounds__(256) void k_agg1() {
    int gw   = (blockIdx.x * blockDim.x + threadIdx.x) >> 5;
    int lane = threadIdx.x & 31;
    if (gw >= N1V) return;
    int beg = g_off1[gw], d = g_deg1[gw];
    uint32_t p0 = 0, p1 = 0, p2 = 0, p3 = 0, p4 = 0, p5 = 0, p6 = 0;
    bool act = (lane < WIN);
    int e = 0;
    for (; e + 4 <= d; e += 4) {
        int s0 = __ldg(&g_csr1[beg + e + 0]);
        int s1 = __ldg(&g_csr1[beg + e + 1]);
        int s2 = __ldg(&g_csr1[beg + e + 2]);
        int s3 = __ldg(&g_csr1[beg + e + 3]);
        uint32_t c0 = act ? __ldg(&g_xb[(size_t)s0 * WSTR + lane]) : 0u;
        uint32_t c1 = act ? __ldg(&g_xb[(size_t)s1 * WSTR + lane]) : 0u;
        uint32_t c2 = act ? __ldg(&g_xb[(size_t)s2 * WSTR + lane]) : 0u;
        uint32_t c3 = act ? __ldg(&g_xb[(size_t)s3 * WSTR + lane]) : 0u;
        RIPPLE(c0); RIPPLE(c1); RIPPLE(c2); RIPPLE(c3);
    }
    for (; e < d; e++) {
        int s = __ldg(&g_csr1[beg + e]);
        uint32_t c = act ? __ldg(&g_xb[(size_t)s * WSTR + lane]) : 0u;
        RIPPLE(c);
    }
    if (act) {
        uint32_t xw = g_xb[(size_t)gw * WSTR + lane];
        uint32_t* outw = (uint32_t*)(g_cA + (size_t)gw * KA);
#pragma unroll
        for (int w = 0; w < 8; w++) {
            uint32_t cw =  spread4(p0 >> (4 * w))
                        | (spread4(p1 >> (4 * w)) << 1)
                        | (spread4(p2 >> (4 * w)) << 2)
                        | (spread4(p3 >> (4 * w)) << 3)
                        | (spread4(p4 >> (4 * w)) << 4)
                        | (spread4(p5 >> (4 * w)) << 5)
                        | (spread4(p6 >> (4 * w)) << 6);
            uint32_t sp = spread4(xw >> (4 * w));
            uint32_t sw = sp | ((sp ^ 0x01010101u) * 0xFFu);  // bit->+1, else -1
            int f0 = lane * 32 + w * 4;
            int vnum = FIN - f0;
            uint32_t vm = (vnum >= 4) ? 0xFFFFFFFFu :
                          ((vnum <= 0) ? 0u : ((1u << (8 * vnum)) - 1u));
            outw[lane * 8 + w]       = cw;
            outw[152 + lane * 8 + w] = sw & vm;
        }
    }
}

// layer-1 GEMM on tensor cores (R8-proven config)
__global__ __launch_bounds__(512) void k_gemm1m(const float* __restrict__ bias1) {
    __shared__ float sh[32][257];
    int tid = threadIdx.x, lane = tid & 31, wid = tid >> 5;
    int warp_m = wid & 3, warp_n = wid >> 2;     // 4M x 4N warps
    int g = lane >> 2, t = lane & 3;
    int m0 = blockIdx.x * 64 + warp_m * 16;
    int n0 = warp_n * 64;

    int acc1[8][4], acc2[8][4];
#pragma unroll
    for (int f = 0; f < 8; f++)
#pragma unroll
        for (int i = 0; i < 4; i++) { acc1[f][i] = 0; acc2[f][i] = 0; }

    const int8_t* Ar0 = g_cA + (size_t)(m0 + g) * KA;
    const int8_t* Ar1 = Ar0 + (size_t)8 * KA;

#define K_HALF(ACC, KBASE)                                                      \
    for (int ks = 0; ks < 19; ks++) {                                           \
        int k0 = (KBASE) + ks * 32 + 4 * t;                                     \
        int a0 = *(const int*)(Ar0 + k0);                                       \
        int a1 = *(const int*)(Ar1 + k0);                                       \
        int a2 = *(const int*)(Ar0 + k0 + 16);                                  \
        int a3 = *(const int*)(Ar1 + k0 + 16);                                  \
        _Pragma("unroll")                                                       \
        for (int f = 0; f < 8; f++) {                                           \
            const int8_t* Bp = g_sw + (size_t)(n0 + f * 8 + g) * KA + k0;       \
            int b0 = *(const int*)Bp;                                           \
            int b1 = *(const int*)(Bp + 16);                                    \
            MMA_S8(ACC[f], a0, a1, a2, a3, b0, b1);                             \
        }                                                                       \
    }
    K_HALF(acc1, 0)
    K_HALF(acc2, 608)
#undef K_HALF

    int rg0 = m0 + g;
    int cnt0 = g_deg1[rg0], cnt1 = g_deg1[rg0 + 8];
    float rc0 = cnt0 ? (1.f / (float)cnt0) : 1.f;
    float rc1 = cnt1 ? (1.f / (float)cnt1) : 1.f;

    for (int ph = 0; ph < 2; ph++) {
        if ((warp_m >> 1) == ph) {
            int rl = (warp_m & 1) * 16 + g;
#pragma unroll
            for (int f = 0; f < 8; f++) {
#pragma unroll
                for (int i = 0; i < 4; i++) {
                    int col = n0 + f * 8 + 2 * t + (i & 1);
                    int cnt = (i < 2) ? cnt0 : cnt1;
                    float rc = (i < 2) ? rc0 : rc1;
                    int r = (i < 2) ? rl : rl + 8;
                    float v = g_al1[col] * (float)(2 * acc1[f][i] - cnt * g_ws1[col]) * rc
                            + g_ar1[col] * (float)acc2[f][i] + bias1[col];
                    sh[r][col] = fmaxf(v, 0.f);
                }
            }
        }
        __syncthreads();
#pragma unroll
        for (int rr = 0; rr < 2; rr++) {
            int r = wid * 2 + rr;
            float hv[8]; float s = 0.f;
#pragma unroll
            for (int q = 0; q < 8; q++) { hv[q] = sh[r][q * 32 + lane]; s += hv[q]; }
            for (int o = 16; o; o >>= 1) s += __shfl_xor_sync(0xffffffffu, s, o);
            float mean = s * (1.f / (float)FH);
            int grow = blockIdx.x * 64 + ph * 32 + r;
#pragma unroll
            for (int q = 0; q < 8; q++) {
                uint32_t bits = __ballot_sync(0xffffffffu, hv[q] > mean);
                if (lane == q) g_hb[grow * WH + q] = bits;
            }
        }
        __syncthreads();
    }
}

// fused layer 2 + tail re-zero of degree arrays (replaces k_init)
__global__ __launch_bounds__(64) void k_l2(const float* __restrict__ b2,
                                           float* __restrict__ out) {
    int i = blockIdx.x, tid = threadIdx.x;
    __shared__ __align__(16) uint32_t sa[NPL * WH];
    __shared__ __align__(16) uint32_t sx[WH];
    __shared__ int sPA[NPL];
    __shared__ float vals[FOUT];
    __shared__ float slse;

    int cnt = g_deg2[i];
    if (tid < WH) sx[tid] = g_hb[(size_t)i * WH + tid];

    if (tid < 32) {
        int lane = tid;
        int beg = g_off2[i];
        uint32_t p0 = 0, p1 = 0, p2 = 0, p3 = 0, p4 = 0, p5 = 0, p6 = 0;
        bool act = (lane < WH);
        int e = 0;
        for (; e + 4 <= cnt; e += 4) {
            int s0 = __ldg(&g_csr2[beg + e + 0]);
            int s1 = __ldg(&g_csr2[beg + e + 1]);
            int s2 = __ldg(&g_csr2[beg + e + 2]);
            int s3 = __ldg(&g_csr2[beg + e + 3]);
            uint32_t c0 = act ? __ldg(&g_hb[(size_t)s0 * WH + lane]) : 0u;
            uint32_t c1 = act ? __ldg(&g_hb[(size_t)s1 * WH + lane]) : 0u;
            uint32_t c2 = act ? __ldg(&g_hb[(size_t)s2 * WH + lane]) : 0u;
            uint32_t c3 = act ? __ldg(&g_hb[(size_t)s3 * WH + lane]) : 0u;
            RIPPLE(c0); RIPPLE(c1); RIPPLE(c2); RIPPLE(c3);
        }
        for (; e < cnt; e++) {
            int s = __ldg(&g_csr2[beg + e]);
            uint32_t c = act ? __ldg(&g_hb[(size_t)s * WH + lane]) : 0u;
            RIPPLE(c);
        }
        if (act) {
            sa[0 * WH + lane] = p0; sa[1 * WH + lane] = p1;
            sa[2 * WH + lane] = p2; sa[3 * WH + lane] = p3;
            sa[4 * WH + lane] = p4; sa[5 * WH + lane] = p5;
            sa[6 * WH + lane] = p6;
        }
        int pa;
        pa = __reduce_add_sync(0xffffffffu, __popc(p0)); if (!lane) sPA[0] = pa;
        pa = __reduce_add_sync(0xffffffffu, __popc(p1)); if (!lane) sPA[1] = pa;
        pa = __reduce_add_sync(0xffffffffu, __popc(p2)); if (!lane) sPA[2] = pa;
        pa = __reduce_add_sync(0xffffffffu, __popc(p3)); if (!lane) sPA[3] = pa;
        pa = __reduce_add_sync(0xffffffffu, __popc(p4)); if (!lane) sPA[4] = pa;
        pa = __reduce_add_sync(0xffffffffu, __popc(p5)); if (!lane) sPA[5] = pa;
        pa = __reduce_add_sync(0xffffffffu, __popc(p6)); if (!lane) sPA[6] = pa;
    }
    __syncthreads();

    if (tid < FOUT) {
        int j = tid;
        const uint4* wlp = (const uint4*)&g_wl2[j * WH];
        const uint4* wrp = (const uint4*)&g_wr2[j * WH];
        uint4 wlA = wlp[0], wlB = wlp[1];
        uint4 wrA = wrp[0], wrB = wrp[1];
        int np = (cnt > 0) ? (32 - __clz(cnt)) : 0;
        int CW = 0;
        for (int p = 0; p < np; p++) {
            const uint4* ap = (const uint4*)&sa[p * WH];
            uint4 aA = ap[0], aB = ap[1];
            int s = __popc(aA.x & wlA.x) + __popc(aA.y & wlA.y) +
                    __popc(aA.z & wlA.z) + __popc(aA.w & wlA.w) +
                    __popc(aB.x & wlB.x) + __popc(aB.y & wlB.y) +
                    __popc(aB.z & wlB.z) + __popc(aB.w & wlB.w);
            CW += (2 * s - sPA[p]) * (1 << p);
        }
        const uint4* xp = (const uint4*)sx;
        uint4 xA = xp[0], xB = xp[1];
        int x2 = __popc(xA.x ^ wrA.x) + __popc(xA.y ^ wrA.y) +
                 __popc(xA.z ^ wrA.z) + __popc(xA.w ^ wrA.w) +
                 __popc(xB.x ^ wrB.x) + __popc(xB.y ^ wrB.y) +
                 __popc(xB.z ^ wrB.z) + __popc(xB.w ^ wrB.w);
        int dot2 = FH - 2 * x2;
        float rc = (cnt > 0) ? (1.f / (float)cnt) : 1.f;
        float v = (float)(2 * CW - cnt * g_ws2[j]) * rc * g_al2[j]
                + (float)dot2 * g_ar2[j] + b2[j];
        vals[j] = v;
    }
    __syncthreads();
    if (tid == 0) {
        float m = vals[0];
        for (int k = 1; k < FOUT; k++) m = fmaxf(m, vals[k]);
        float se = 0.f;
        for (int k = 0; k < FOUT; k++) se += expf(vals[k] - m);
        slse = m + logf(se);
    }
    __syncthreads();
    if (tid < FOUT) out[i * FOUT + tid] = vals[tid] - slse;
    // tail: re-zero degree arrays for the next replay (readers are done)
    if (tid < 11) g_deg1[i * 11 + tid] = 0;
    if (tid == 11) g_deg2[i] = 0;
}

// ---------------- host launcher (R8 topology; agg1 at ncu idx 5) ----------
extern "C" void kernel_launch(void* const* d_in, const int* in_sizes, int n_in,
                              void* d_out, int out_size) {
    const float* x = nullptr;
    const void *ei1 = nullptr, *ei2 = nullptr;
    const float *W1l = nullptr, *W1r = nullptr, *b1 = nullptr;
    const float *W2l = nullptr, *W2r = nullptr, *b2 = nullptr;
    int c1 = 0, c2 = 0;
    for (int i = 0; i < n_in; i++) {
        switch (in_sizes[i]) {
            case 176304128: x   = (const float*)d_in[i]; break;
            case 563200:    ei1 = d_in[i]; break;
            case 20480:     ei2 = d_in[i]; break;
            case 154112:    if (c1++ == 0) W1l = (const float*)d_in[i];
                            else           W1r = (const float*)d_in[i]; break;
            case 256:       b1  = (const float*)d_in[i]; break;
            case 10496:     if (c2++ == 0) W2l = (const float*)d_in[i];
                            else           W2r = (const float*)d_in[i]; break;
            case 41:        b2  = (const float*)d_in[i]; break;
            default: break;
        }
    }

    static cudaStream_t sCsr = nullptr, sW = nullptr;
    static cudaEvent_t evStart = nullptr, evHist = nullptr, evCsr = nullptr, evW = nullptr;
    if (!sCsr) {
        cudaStreamCreateWithFlags(&sCsr, cudaStreamNonBlocking);
        cudaStreamCreateWithFlags(&sW,   cudaStreamNonBlocking);
        cudaEventCreateWithFlags(&evStart, cudaEventDisableTiming);
        cudaEventCreateWithFlags(&evHist,  cudaEventDisableTiming);
        cudaEventCreateWithFlags(&evCsr,   cudaEventDisableTiming);
        cudaEventCreateWithFlags(&evW,     cudaEventDisableTiming);
    }
    cudaStream_t m = 0;

    // weights branch (independent)
    cudaEventRecord(evStart, m);
    cudaStreamWaitEvent(sW, evStart, 0);
    k_weights<<<75, 256, 0, sW>>>(W1l, W1r, W2l, W2r);        // launch 0
    cudaEventRecord(evW, sW);

    k_hist<<<(E1V + 255) / 256, 256, 0, m>>>(ei1, ei2);       // launch 1
    cudaEventRecord(evHist, m);

    // CSR branch runs under k_bin's DRAM-bound window
    cudaStreamWaitEvent(sCsr, evHist, 0);
    k_scan<<<2, 1024, 0, sCsr>>>();                           // launch 2
    k_scatter<<<(E1V + 255) / 256, 256, 0, sCsr>>>(ei1, ei2); // launch 3
    cudaEventRecord(evCsr, sCsr);

    k_bin<<<N0 / 8, 256, 0, m>>>(x);                          // launch 4

    cudaStreamWaitEvent(m, evCsr, 0);
    k_agg1<<<N1V / 8, 256, 0, m>>>();                         // launch 5 <- ncu -s 5
    cudaStreamWaitEvent(m, evW, 0);
    k_gemm1m<<<N1V / 64, 512, 0, m>>>(b1);                    // launch 6
    k_l2<<<NBV, 64, 0, m>>>(b2, (float*)d_out);               // launch 7
}